// round 6
// baseline (speedup 1.0000x reference)
#include <cuda_runtime.h>
#include <math.h>
#include <stdint.h>

#define Dm   1024
#define Hh   16
#define DKk  64
#define Bb   4
#define Ll   2048
#define MTOT (Bb * Ll)   // 8192

#define NPLANE ((size_t)MTOT * Dm)   // 8388608 elems
#define WPLANE ((size_t)Dm * Dm)     // 1048576

// One big bf16 scratch buffer (no allocations allowed): 240 MB
// planes 0-5 : split of raw activations q,k,v (hi,lo each)
// planes 6-11: projection outputs Q,K,V (hi,lo)
// planes 12-13: attention context (hi,lo)
// then 8 weight planes (wq,wk,wv,wo hi/lo)
__device__ __align__(16) uint16_t g_buf[14 * NPLANE + 8 * WPLANE];

__device__ __forceinline__ uint32_t smem_u32(const void* p) {
    uint32_t a;
    asm("{ .reg .u64 t; cvta.to.shared.u64 t, %1; cvt.u32.u64 %0, t; }"
        : "=r"(a) : "l"(p));
    return a;
}

// Split two fp32 into packed bf16 hi-pair and lo-pair (x0 -> low half).
__device__ __forceinline__ void split2(float x0, float x1,
                                       uint32_t& hi, uint32_t& lo) {
    uint32_t h;
    asm("cvt.rn.bf16x2.f32 %0, %1, %2;" : "=r"(h) : "f"(x1), "f"(x0));
    const float f0 = __uint_as_float(h << 16);
    const float f1 = __uint_as_float(h & 0xffff0000u);
    uint32_t l;
    asm("cvt.rn.bf16x2.f32 %0, %1, %2;" : "=r"(l) : "f"(x1 - f1), "f"(x0 - f0));
    hi = h; lo = l;
}

__device__ __forceinline__ void mma_bf16(float d[4], const uint32_t a[4],
                                         const uint32_t b[2]) {
    asm volatile(
        "mma.sync.aligned.m16n8k16.row.col.f32.bf16.bf16.f32 "
        "{%0,%1,%2,%3}, {%4,%5,%6,%7}, {%8,%9}, {%0,%1,%2,%3};"
        : "+f"(d[0]), "+f"(d[1]), "+f"(d[2]), "+f"(d[3])
        : "r"(a[0]), "r"(a[1]), "r"(a[2]), "r"(a[3]), "r"(b[0]), "r"(b[1]));
}

__device__ __forceinline__ void ldsm_x2(uint32_t& d0, uint32_t& d1, uint32_t a) {
    asm volatile("ldmatrix.sync.aligned.m8n8.x2.shared.b16 {%0,%1}, [%2];"
                 : "=r"(d0), "=r"(d1) : "r"(a));
}
__device__ __forceinline__ void ldsm_x2_t(uint32_t& d0, uint32_t& d1, uint32_t a) {
    asm volatile("ldmatrix.sync.aligned.m8n8.x2.trans.shared.b16 {%0,%1}, [%2];"
                 : "=r"(d0), "=r"(d1) : "r"(a));
}

#define CP16(smaddr, gptr) \
    asm volatile("cp.async.cg.shared.global [%0], [%1], 16;" \
                 :: "r"(smaddr), "l"(gptr))

// ---------------------------------------------------------------------------
// fp32 -> bf16 hi/lo plane split
// ---------------------------------------------------------------------------
__global__ __launch_bounds__(256)
void split_bf16(const float* __restrict__ in, uint16_t* __restrict__ hi,
                uint16_t* __restrict__ lo, int n8)
{
    const int i = blockIdx.x * 256 + threadIdx.x;
    if (i < n8) {
        const float4* in4 = (const float4*)in;
        float4 a = in4[2 * i], b = in4[2 * i + 1];
        uint4 H, L;
        split2(a.x, a.y, H.x, L.x);
        split2(a.z, a.w, H.y, L.y);
        split2(b.x, b.y, H.z, L.z);
        split2(b.z, b.w, H.w, L.w);
        ((uint4*)hi)[i] = H;
        ((uint4*)lo)[i] = L;
    }
}

// ---------------------------------------------------------------------------
// split-bf16 GEMM: C[M,N] = A[M,K] @ W[N,K]^T + bias (3-product hi/lo).
// 256 thr / 8 warps (2m x 4n), warp tile 64x32, K chunks of 32, dbl-buffer.
// smem rows padded to 80B (20 u32) -> conflict-free fragment LDS.
// ---------------------------------------------------------------------------
#define GK      1024
#define GN      1024
#define KCH     32
#define NCHUNK  (GK / KCH)
#define GSTRIDE 20                     // u32 per smem row
#define GPLANE  (128 * GSTRIDE)        // 2560 u32 per plane
#define GSTAGE  (4 * GPLANE)           // Ahi,Alo,Bhi,Blo
#define GEMM_SMEM_BYTES (2 * GSTAGE * 4)   // 81920

__global__ __launch_bounds__(256, 2)
void gemm_bf16s(const uint16_t* __restrict__ Ah, const uint16_t* __restrict__ Al,
                const uint16_t* __restrict__ Bh, const uint16_t* __restrict__ Bl,
                const float* __restrict__ bias,
                float* __restrict__ Cf,
                uint16_t* __restrict__ Ch, uint16_t* __restrict__ Cl,
                float scale)
{
    extern __shared__ uint32_t smu[];
    const int tid  = threadIdx.x;
    const int warp = tid >> 5;
    const int lane = tid & 31;
    const int wm   = warp & 1;
    const int wn   = warp >> 1;        // 0..3
    const int m0   = blockIdx.y * 128;
    const int n0   = blockIdx.x * 128;
    const int frow = tid >> 2;         // 0..63
    const int fseg = tid & 3;

    float d[4][4][4];
    #pragma unroll
    for (int mi = 0; mi < 4; mi++)
        #pragma unroll
        for (int ni = 0; ni < 4; ni++)
            #pragma unroll
            for (int x = 0; x < 4; x++) d[mi][ni][x] = 0.f;

    auto fill = [&](int c, int s) {
        const int k0 = c * KCH;
        const uint32_t base = smem_u32(smu + s * GSTAGE);
        #pragma unroll
        for (int i = 0; i < 2; i++) {
            const int r = frow + i * 64;
            const uint32_t so = (uint32_t)(r * 80 + fseg * 16);
            CP16(base + 0 * GPLANE * 4 + so, Ah + (size_t)(m0 + r) * GK + k0 + fseg * 8);
            CP16(base + 1 * GPLANE * 4 + so, Al + (size_t)(m0 + r) * GK + k0 + fseg * 8);
            CP16(base + 2 * GPLANE * 4 + so, Bh + (size_t)(n0 + r) * GK + k0 + fseg * 8);
            CP16(base + 3 * GPLANE * 4 + so, Bl + (size_t)(n0 + r) * GK + k0 + fseg * 8);
        }
        asm volatile("cp.async.commit_group;");
    };

    fill(0, 0);
    fill(1, 1);

    for (int c = 0; c < NCHUNK; c++) {
        const int s = c & 1;
        asm volatile("cp.async.wait_group 1;" ::: "memory");
        __syncthreads();

        const uint32_t* st  = smu + s * GSTAGE;
        const uint32_t* pAh = st + (wm * 64 + (lane >> 2)) * GSTRIDE + (lane & 3);
        const uint32_t* pAl = pAh + GPLANE;
        const uint32_t* pBh = st + 2 * GPLANE +
                              (wn * 32 + (lane >> 2)) * GSTRIDE + (lane & 3);
        const uint32_t* pBl = pBh + GPLANE;

        #pragma unroll
        for (int j = 0; j < 2; j++) {          // two k16 steps per chunk
            uint32_t ah[4][4], al[4][4];
            #pragma unroll
            for (int mi = 0; mi < 4; mi++) {
                const uint32_t* p = pAh + mi * 16 * GSTRIDE + j * 8;
                ah[mi][0] = p[0];
                ah[mi][1] = p[8 * GSTRIDE];
                ah[mi][2] = p[4];
                ah[mi][3] = p[8 * GSTRIDE + 4];
                const uint32_t* q2 = pAl + mi * 16 * GSTRIDE + j * 8;
                al[mi][0] = q2[0];
                al[mi][1] = q2[8 * GSTRIDE];
                al[mi][2] = q2[4];
                al[mi][3] = q2[8 * GSTRIDE + 4];
            }
            #pragma unroll
            for (int ni = 0; ni < 4; ni++) {
                const uint32_t* pb = pBh + ni * 8 * GSTRIDE + j * 8;
                uint32_t bh[2] = {pb[0], pb[4]};
                #pragma unroll
                for (int mi = 0; mi < 4; mi++) mma_bf16(d[mi][ni], ah[mi], bh);
                #pragma unroll
                for (int mi = 0; mi < 4; mi++) mma_bf16(d[mi][ni], al[mi], bh);
                const uint32_t* pl2 = pBl + ni * 8 * GSTRIDE + j * 8;
                uint32_t bl[2] = {pl2[0], pl2[4]};
                #pragma unroll
                for (int mi = 0; mi < 4; mi++) mma_bf16(d[mi][ni], ah[mi], bl);
            }
        }
        __syncthreads();
        if (c + 2 < NCHUNK) fill(c + 2, s);
    }

    const int row0 = m0 + wm * 64 + (lane >> 2);
    const int colb = n0 + wn * 32 + 2 * (lane & 3);
    #pragma unroll
    for (int ni = 0; ni < 4; ni++) {
        const int c = colb + ni * 8;
        const float b0 = bias[c], b1 = bias[c + 1];
        #pragma unroll
        for (int mi = 0; mi < 4; mi++) {
            #pragma unroll
            for (int half = 0; half < 2; half++) {
                const int r = row0 + mi * 16 + 8 * half;
                const float v0 = d[mi][ni][2 * half]     + b0;
                const float v1 = d[mi][ni][2 * half + 1] + b1;
                if (Cf) {
                    float2 w = {v0, v1};
                    *(float2*)(Cf + (size_t)r * GN + c) = w;
                } else {
                    uint32_t hv, lv;
                    split2(v0 * scale, v1 * scale, hv, lv);
                    ((uint32_t*)Ch)[(size_t)r * (GN / 2) + c / 2] = hv;
                    ((uint32_t*)Cl)[(size_t)r * (GN / 2) + c / 2] = lv;
                }
            }
        }
    }
}

// ---------------------------------------------------------------------------
// Flash attention (causal), split-bf16 MMAs.
// Block = (b, h, 128-row q tile); 256 thr / 8 warps; 64-key iterations.
// Q planes pre-scaled by 1/8 in the Q projection epilogue.
// smem u32 layout:
//   [0, ASTAGE)            stage1 KV (Kh,Kl,Vh,Vl) — Q staging in prologue
//   [ASTAGE, 2*ASTAGE)     stage0 KV
//   [2*ASTAGE, +2*AQPL)    P planes (Ph, Pl)
// ---------------------------------------------------------------------------
#define AST     36                  // u32 per row (144 B)
#define APL     (64 * AST)          // KV plane u32 (2304)
#define ASTAGE  (4 * APL)           // 9216 u32 = 36864 B
#define AQPL    (128 * AST)         // Q/P plane u32 (4608)
#define OFF_ST1U 0
#define OFF_ST0U ASTAGE
#define OFF_PU   (2 * ASTAGE)
#define ATT_SMEM_BYTES ((2 * ASTAGE + 2 * AQPL) * 4)   // 110592

__global__ __launch_bounds__(256, 2)
void attn_bf16s(const uint16_t* __restrict__ Qh, const uint16_t* __restrict__ Ql,
                const uint16_t* __restrict__ Kh, const uint16_t* __restrict__ Kl,
                const uint16_t* __restrict__ Vh, const uint16_t* __restrict__ Vl,
                uint16_t* __restrict__ Ch, uint16_t* __restrict__ Cl)
{
    extern __shared__ uint32_t smu[];
    const int tid  = threadIdx.x;
    const int lane = tid & 31;
    const int warp = tid >> 5;
    const int r    = lane >> 2;
    const int cth  = lane & 3;
    const int qi   = gridDim.x - 1 - blockIdx.x;   // heavy tiles first
    const int hd   = blockIdx.y;
    const int b    = blockIdx.z;
    const int q0   = qi * 128;

    const uint32_t smub = smem_u32(smu);
    const int l15 = lane & 15;
    const uint32_t k_lane_off = (uint32_t)((l15 & 7) * 144 + (l15 >> 3) * 16);
    const uint32_t v_lane_off = (uint32_t)(l15 * 144);

    const size_t hoff = (size_t)hd * 64;

    // Prologue: Q planes into ST1 area (group 0)
    #pragma unroll
    for (int i = 0; i < 4; i++) {
        const int id  = tid + i * 256;       // 0..1023
        const int row = id >> 3, seg = id & 7;
        const uint32_t so = (uint32_t)(row * 144 + seg * 16);
        CP16(smub + so, Qh + ((size_t)(b * Ll + q0 + row)) * Dm + hoff + seg * 8);
        CP16(smub + AQPL * 4 + so,
             Ql + ((size_t)(b * Ll + q0 + row)) * Dm + hoff + seg * 8);
    }
    asm volatile("cp.async.commit_group;");

    auto fillKV = [&](int kt, uint32_t dstB) {
        const int k0 = kt * 64;
        #pragma unroll
        for (int i = 0; i < 2; i++) {
            const int id  = tid + i * 256;   // 0..511
            const int row = id >> 3, seg = id & 7;
            const uint32_t so = (uint32_t)(row * 144 + seg * 16);
            const size_t g = ((size_t)(b * Ll + k0 + row)) * Dm + hoff + seg * 8;
            CP16(dstB + 0 * APL * 4 + so, Kh + g);
            CP16(dstB + 1 * APL * 4 + so, Kl + g);
            CP16(dstB + 2 * APL * 4 + so, Vh + g);
            CP16(dstB + 3 * APL * 4 + so, Vl + g);
        }
        asm volatile("cp.async.commit_group;");
    };

    fillKV(0, smub + OFF_ST0U * 4);

    asm volatile("cp.async.wait_group 1;" ::: "memory");
    __syncthreads();

    // Preload Q fragments (hi + lo)
    uint32_t qh[4][4], ql[4][4];
    {
        const uint32_t* qb = smu + (warp * 16 + r) * AST + cth;
        const uint32_t* qc = qb + AQPL;
        #pragma unroll
        for (int j = 0; j < 4; j++) {
            qh[j][0] = qb[j * 8];
            qh[j][1] = qb[8 * AST + j * 8];
            qh[j][2] = qb[j * 8 + 4];
            qh[j][3] = qb[8 * AST + j * 8 + 4];
            ql[j][0] = qc[j * 8];
            ql[j][1] = qc[8 * AST + j * 8];
            ql[j][2] = qc[j * 8 + 4];
            ql[j][3] = qc[8 * AST + j * 8 + 4];
        }
    }
    __syncthreads();

    const int ktmax = 2 * qi + 2;
    if (ktmax > 1) fillKV(1, smub + OFF_ST1U * 4);

    float m_i[2] = {-1e30f, -1e30f};
    float l_i[2] = {0.f, 0.f};
    float o[8][4];
    #pragma unroll
    for (int ni = 0; ni < 8; ni++)
        #pragma unroll
        for (int x = 0; x < 4; x++) o[ni][x] = 0.f;

    for (int kt = 0; kt < ktmax; kt++) {
        const int s = kt & 1;
        const uint32_t stB = smub + (s ? OFF_ST1U : OFF_ST0U) * 4;

        asm volatile("cp.async.wait_group 1;" ::: "memory");
        __syncthreads();

        // S = (Q/8) K^T  (3-product split-bf16)
        float sacc[8][4];
        #pragma unroll
        for (int ni = 0; ni < 8; ni++)
            #pragma unroll
            for (int x = 0; x < 4; x++) sacc[ni][x] = 0.f;

        #pragma unroll
        for (int j = 0; j < 4; j++) {
            #pragma unroll
            for (int ni = 0; ni < 8; ni++) {
                const uint32_t ka = stB + (uint32_t)(ni * 1152 + j * 32) + k_lane_off;
                uint32_t b0, b1, c0, c1;
                ldsm_x2(b0, b1, ka);
                ldsm_x2(c0, c1, ka + APL * 4);
                uint32_t bh[2] = {b0, b1};
                mma_bf16(sacc[ni], qh[j], bh);
                mma_bf16(sacc[ni], ql[j], bh);
                uint32_t bl[2] = {c0, c1};
                mma_bf16(sacc[ni], qh[j], bl);
            }
        }

        const int k0 = kt * 64;
        if (k0 + 63 > q0) {      // causal mask near diagonal
            const int rowb = q0 + warp * 16 + r;
            #pragma unroll
            for (int ni = 0; ni < 8; ni++) {
                const int colb = k0 + ni * 8 + 2 * cth;
                #pragma unroll
                for (int x = 0; x < 4; x++) {
                    const int row = rowb + 8 * (x >> 1);
                    const int col = colb + (x & 1);
                    if (col > row) sacc[ni][x] = -1e30f;
                }
            }
        }

        // online softmax; P split to bf16 hi/lo planes
        #pragma unroll
        for (int h = 0; h < 2; h++) {
            float mx = -1e30f;
            #pragma unroll
            for (int ni = 0; ni < 8; ni++)
                mx = fmaxf(mx, fmaxf(sacc[ni][2 * h], sacc[ni][2 * h + 1]));
            mx = fmaxf(mx, __shfl_xor_sync(0xffffffffu, mx, 1));
            mx = fmaxf(mx, __shfl_xor_sync(0xffffffffu, mx, 2));
            const float mnew  = fmaxf(m_i[h], mx);
            const float alpha = __expf(m_i[h] - mnew);
            float sum = 0.f;
            const int prow = warp * 16 + r + 8 * h;
            #pragma unroll
            for (int ni = 0; ni < 8; ni++) {
                const float p0 = __expf(sacc[ni][2 * h] - mnew);
                const float p1 = __expf(sacc[ni][2 * h + 1] - mnew);
                sum += p0 + p1;
                uint32_t hv, lv;
                split2(p0, p1, hv, lv);
                smu[OFF_PU + prow * AST + ni * 4 + cth] = hv;
                smu[OFF_PU + AQPL + prow * AST + ni * 4 + cth] = lv;
                o[ni][2 * h]     *= alpha;
                o[ni][2 * h + 1] *= alpha;
            }
            sum += __shfl_xor_sync(0xffffffffu, sum, 1);
            sum += __shfl_xor_sync(0xffffffffu, sum, 2);
            l_i[h] = l_i[h] * alpha + sum;
            m_i[h] = mnew;
        }
        __syncwarp();

        // O += P V  (V via ldmatrix.trans; 3-product split)
        const uint32_t vB = stB + 2 * APL * 4;
        const uint32_t* pa0 = smu + OFF_PU + (warp * 16 + r) * AST + cth;
        #pragma unroll
        for (int kk = 0; kk < 4; kk++) {
            uint32_t ah[4], al[4];
            const uint32_t* pa = pa0 + kk * 8;
            ah[0] = pa[0];
            ah[1] = pa[8 * AST];
            ah[2] = pa[4];
            ah[3] = pa[8 * AST + 4];
            const uint32_t* pl2 = pa + AQPL;
            al[0] = pl2[0];
            al[1] = pl2[8 * AST];
            al[2] = pl2[4];
            al[3] = pl2[8 * AST + 4];
            #pragma unroll
            for (int ni = 0; ni < 8; ni++) {
                const uint32_t va = vB + (uint32_t)(kk * 2304 + ni * 16) + v_lane_off;
                uint32_t b0, b1, c0, c1;
                ldsm_x2_t(b0, b1, va);
                uint32_t bh[2] = {b0, b1};
                mma_bf16(o[ni], ah, bh);
                mma_bf16(o[ni], al, bh);
                ldsm_x2_t(c0, c1, va + APL * 4);
                uint32_t bl[2] = {c0, c1};
                mma_bf16(o[ni], ah, bl);
            }
        }

        __syncthreads();
        if (kt + 2 < ktmax) fillKV(kt + 2, smub + (s ? OFF_ST1U : OFF_ST0U) * 4);
        else asm volatile("cp.async.commit_group;");
    }

    // normalize + split + write context planes
    #pragma unroll
    for (int h = 0; h < 2; h++) {
        const float inv = 1.0f / l_i[h];
        const int row = q0 + warp * 16 + r + 8 * h;
        const size_t base = ((size_t)(b * Ll + row)) * (Dm / 2) + hd * 32;
        #pragma unroll
        for (int ni = 0; ni < 8; ni++) {
            uint32_t hv, lv;
            split2(o[ni][2 * h] * inv, o[ni][2 * h + 1] * inv, hv, lv);
            ((uint32_t*)Ch)[base + ni * 4 + cth] = hv;
            ((uint32_t*)Cl)[base + ni * 4 + cth] = lv;
        }
    }
}

// ---------------------------------------------------------------------------
extern "C" void kernel_launch(void* const* d_in, const int* in_sizes, int n_in,
                              void* d_out, int out_size)
{
    const float* q    = (const float*)d_in[0];
    const float* k    = (const float*)d_in[1];
    const float* v    = (const float*)d_in[2];
    const float* wq_w = (const float*)d_in[3];
    const float* wq_b = (const float*)d_in[4];
    const float* wk_w = (const float*)d_in[5];
    const float* wk_b = (const float*)d_in[6];
    const float* wv_w = (const float*)d_in[7];
    const float* wv_b = (const float*)d_in[8];
    const float* wo_w = (const float*)d_in[9];
    const float* wo_b = (const float*)d_in[10];
    float* out = (float*)d_out;

    uint16_t* P;
    cudaGetSymbolAddress((void**)&P, g_buf);
    uint16_t* W = P + 14 * NPLANE;
    #define PLN(i) (P + (size_t)(i) * NPLANE)
    #define WPL(i) (W + (size_t)(i) * WPLANE)

    cudaFuncSetAttribute(gemm_bf16s, cudaFuncAttributeMaxDynamicSharedMemorySize,
                         GEMM_SMEM_BYTES);
    cudaFuncSetAttribute(attn_bf16s, cudaFuncAttributeMaxDynamicSharedMemorySize,
                         ATT_SMEM_BYTES);

    const int n8a = (int)(NPLANE / 8);   // 1048576
    const int n8w = (int)(WPLANE / 8);   // 131072
    split_bf16<<<n8a / 256, 256>>>(q, PLN(0), PLN(1), n8a);
    split_bf16<<<n8a / 256, 256>>>(k, PLN(2), PLN(3), n8a);
    split_bf16<<<n8a / 256, 256>>>(v, PLN(4), PLN(5), n8a);
    split_bf16<<<n8w / 256, 256>>>(wq_w, WPL(0), WPL(1), n8w);
    split_bf16<<<n8w / 256, 256>>>(wk_w, WPL(2), WPL(3), n8w);
    split_bf16<<<n8w / 256, 256>>>(wv_w, WPL(4), WPL(5), n8w);
    split_bf16<<<n8w / 256, 256>>>(wo_w, WPL(6), WPL(7), n8w);

    dim3 gg(GN / 128, MTOT / 128);   // (8, 64)

    // projections -> bf16 hi/lo planes (Q pre-scaled by 1/8)
    gemm_bf16s<<<gg, 256, GEMM_SMEM_BYTES>>>(PLN(0), PLN(1), WPL(0), WPL(1),
                                             wq_b, nullptr, PLN(6), PLN(7), 0.125f);
    gemm_bf16s<<<gg, 256, GEMM_SMEM_BYTES>>>(PLN(2), PLN(3), WPL(2), WPL(3),
                                             wk_b, nullptr, PLN(8), PLN(9), 1.0f);
    gemm_bf16s<<<gg, 256, GEMM_SMEM_BYTES>>>(PLN(4), PLN(5), WPL(4), WPL(5),
                                             wv_b, nullptr, PLN(10), PLN(11), 1.0f);

    dim3 ga(Ll / 128, Hh, Bb);       // (16, 16, 4)
    attn_bf16s<<<ga, 256, ATT_SMEM_BYTES>>>(PLN(6), PLN(7), PLN(8), PLN(9),
                                            PLN(10), PLN(11), PLN(12), PLN(13));

    // output projection -> fp32 out
    gemm_bf16s<<<gg, 256, GEMM_SMEM_BYTES>>>(PLN(12), PLN(13), WPL(6), WPL(7),
                                             wo_b, out, nullptr, nullptr, 1.0f);
    #undef PLN
    #undef WPL
}

// round 7
// speedup vs baseline: 1.0562x; 1.0562x over previous
#include <cuda_runtime.h>
#include <math.h>
#include <stdint.h>

#define Dm   1024
#define Hh   16
#define DKk  64
#define Bb   4
#define Ll   2048
#define MTOT (Bb * Ll)   // 8192

#define NPLANE ((size_t)MTOT * Dm)   // 8388608 elems
#define WPLANE ((size_t)Dm * Dm)     // 1048576

// One big bf16 scratch buffer (no allocations allowed): 240 MB
__device__ __align__(16) uint16_t g_buf[14 * NPLANE + 8 * WPLANE];

__device__ __forceinline__ uint32_t smem_u32(const void* p) {
    uint32_t a;
    asm("{ .reg .u64 t; cvta.to.shared.u64 t, %1; cvt.u32.u64 %0, t; }"
        : "=r"(a) : "l"(p));
    return a;
}

// Split two fp32 into packed bf16 hi-pair and lo-pair (x0 -> low half).
__device__ __forceinline__ void split2(float x0, float x1,
                                       uint32_t& hi, uint32_t& lo) {
    uint32_t h;
    asm("cvt.rn.bf16x2.f32 %0, %1, %2;" : "=r"(h) : "f"(x1), "f"(x0));
    const float f0 = __uint_as_float(h << 16);
    const float f1 = __uint_as_float(h & 0xffff0000u);
    uint32_t l;
    asm("cvt.rn.bf16x2.f32 %0, %1, %2;" : "=r"(l) : "f"(x1 - f1), "f"(x0 - f0));
    hi = h; lo = l;
}

__device__ __forceinline__ void mma_bf16(float d[4], const uint32_t a[4],
                                         const uint32_t b[2]) {
    asm volatile(
        "mma.sync.aligned.m16n8k16.row.col.f32.bf16.bf16.f32 "
        "{%0,%1,%2,%3}, {%4,%5,%6,%7}, {%8,%9}, {%0,%1,%2,%3};"
        : "+f"(d[0]), "+f"(d[1]), "+f"(d[2]), "+f"(d[3])
        : "r"(a[0]), "r"(a[1]), "r"(a[2]), "r"(a[3]), "r"(b[0]), "r"(b[1]));
}

__device__ __forceinline__ void ldsm_x4(uint32_t r[4], uint32_t a) {
    asm volatile("ldmatrix.sync.aligned.m8n8.x4.shared.b16 {%0,%1,%2,%3}, [%4];"
                 : "=r"(r[0]), "=r"(r[1]), "=r"(r[2]), "=r"(r[3]) : "r"(a));
}
__device__ __forceinline__ void ldsm_x4_t(uint32_t r[4], uint32_t a) {
    asm volatile("ldmatrix.sync.aligned.m8n8.x4.trans.shared.b16 {%0,%1,%2,%3}, [%4];"
                 : "=r"(r[0]), "=r"(r[1]), "=r"(r[2]), "=r"(r[3]) : "r"(a));
}

#define CP16(smaddr, gptr) \
    asm volatile("cp.async.cg.shared.global [%0], [%1], 16;" \
                 :: "r"(smaddr), "l"(gptr))

// ---------------------------------------------------------------------------
// fp32 -> bf16 hi/lo plane split, up to 4 tensors per launch (blockIdx.y)
// ---------------------------------------------------------------------------
struct Split4 {
    const float* in[4];
    uint16_t* hi[4];
    uint16_t* lo[4];
};

__global__ __launch_bounds__(256)
void split_multi(Split4 a, int n8)
{
    const float* in = a.in[blockIdx.y];
    uint16_t* hi = a.hi[blockIdx.y];
    uint16_t* lo = a.lo[blockIdx.y];
    const int i = blockIdx.x * 256 + threadIdx.x;
    if (i < n8) {
        const float4* in4 = (const float4*)in;
        float4 x = in4[2 * i], y = in4[2 * i + 1];
        uint4 H, L;
        split2(x.x, x.y, H.x, L.x);
        split2(x.z, x.w, H.y, L.y);
        split2(y.x, y.y, H.z, L.z);
        split2(y.z, y.w, H.w, L.w);
        ((uint4*)hi)[i] = H;
        ((uint4*)lo)[i] = L;
    }
}

// ---------------------------------------------------------------------------
// split-bf16 GEMM: C[M,N] = A[M,K] @ W[N,K]^T + bias (3-product hi/lo).
// 256 thr / 8 warps (2m x 4n), warp 64x32, K chunks of 32, ldmatrix loads.
// ---------------------------------------------------------------------------
#define GK      1024
#define GN      1024
#define KCH     32
#define NCHUNK  (GK / KCH)
#define GSTRIDE 20                     // u32 per smem row (80 B)
#define GPLANE  (128 * GSTRIDE)        // 2560 u32
#define GSTAGE  (4 * GPLANE)           // Ahi,Alo,Bhi,Blo
#define GEMM_SMEM_BYTES (2 * GSTAGE * 4)   // 81920

__global__ __launch_bounds__(256, 2)
void gemm_bf16s(const uint16_t* __restrict__ Ah, const uint16_t* __restrict__ Al,
                const uint16_t* __restrict__ Bh, const uint16_t* __restrict__ Bl,
                const float* __restrict__ bias,
                float* __restrict__ Cf,
                uint16_t* __restrict__ Ch, uint16_t* __restrict__ Cl,
                float scale)
{
    extern __shared__ uint32_t smu[];
    const int tid  = threadIdx.x;
    const int warp = tid >> 5;
    const int lane = tid & 31;
    const int wm   = warp & 1;
    const int wn   = warp >> 1;        // 0..3
    const int m0   = blockIdx.y * 128;
    const int n0   = blockIdx.x * 128;
    const int frow = tid >> 2;         // 0..63
    const int fseg = tid & 3;

    // ldmatrix lane offsets (bytes)
    const uint32_t aoff = (uint32_t)(((lane & 7) + ((lane >> 3) & 1) * 8) * 80 +
                                     ((lane >> 4) << 4));
    const uint32_t boff = (uint32_t)(((lane & 7) + ((lane >> 4) << 3)) * 80 +
                                     (((lane >> 3) & 1) << 4));
    const uint32_t smub = smem_u32(smu);

    float d[4][4][4];
    #pragma unroll
    for (int mi = 0; mi < 4; mi++)
        #pragma unroll
        for (int ni = 0; ni < 4; ni++)
            #pragma unroll
            for (int x = 0; x < 4; x++) d[mi][ni][x] = 0.f;

    auto fill = [&](int c, int s) {
        const int k0 = c * KCH;
        const uint32_t base = smub + s * GSTAGE * 4;
        #pragma unroll
        for (int i = 0; i < 2; i++) {
            const int r = frow + i * 64;
            const uint32_t so = (uint32_t)(r * 80 + fseg * 16);
            CP16(base + 0 * GPLANE * 4 + so, Ah + (size_t)(m0 + r) * GK + fseg * 8 + k0);
            CP16(base + 1 * GPLANE * 4 + so, Al + (size_t)(m0 + r) * GK + fseg * 8 + k0);
            CP16(base + 2 * GPLANE * 4 + so, Bh + (size_t)(n0 + r) * GK + fseg * 8 + k0);
            CP16(base + 3 * GPLANE * 4 + so, Bl + (size_t)(n0 + r) * GK + fseg * 8 + k0);
        }
        asm volatile("cp.async.commit_group;");
    };

    fill(0, 0);
    fill(1, 1);

    for (int c = 0; c < NCHUNK; c++) {
        const int s = c & 1;
        asm volatile("cp.async.wait_group 1;" ::: "memory");
        __syncthreads();

        const uint32_t stB = smub + s * GSTAGE * 4;
        const uint32_t aA  = stB + (uint32_t)(wm * 64 * 80) + aoff;
        const uint32_t aB  = stB + 2 * GPLANE * 4 + (uint32_t)(wn * 32 * 80) + boff;

        #pragma unroll
        for (int j = 0; j < 2; j++) {
            uint32_t ah[4][4], bh[2][4], bl[2][4];
            #pragma unroll
            for (int mi = 0; mi < 4; mi++)
                ldsm_x4(ah[mi], aA + mi * 1280 + j * 32);
            #pragma unroll
            for (int p = 0; p < 2; p++)
                ldsm_x4(bh[p], aB + 2 * GPLANE * 0 + p * 1280 + j * 32 + GPLANE * 0);
            // product 1: Ah*Bh
            #pragma unroll
            for (int mi = 0; mi < 4; mi++)
                #pragma unroll
                for (int p = 0; p < 2; p++) {
                    mma_bf16(d[mi][2 * p],     ah[mi], &bh[p][0]);
                    mma_bf16(d[mi][2 * p + 1], ah[mi], &bh[p][2]);
                }
            // product 2: Ah*Bl
            #pragma unroll
            for (int p = 0; p < 2; p++)
                ldsm_x4(bl[p], aB + GPLANE * 4 + p * 1280 + j * 32);
            #pragma unroll
            for (int mi = 0; mi < 4; mi++)
                #pragma unroll
                for (int p = 0; p < 2; p++) {
                    mma_bf16(d[mi][2 * p],     ah[mi], &bl[p][0]);
                    mma_bf16(d[mi][2 * p + 1], ah[mi], &bl[p][2]);
                }
            // product 3: Al*Bh (reuse ah regs)
            #pragma unroll
            for (int mi = 0; mi < 4; mi++)
                ldsm_x4(ah[mi], aA + GPLANE * 4 + mi * 1280 + j * 32);
            #pragma unroll
            for (int mi = 0; mi < 4; mi++)
                #pragma unroll
                for (int p = 0; p < 2; p++) {
                    mma_bf16(d[mi][2 * p],     ah[mi], &bh[p][0]);
                    mma_bf16(d[mi][2 * p + 1], ah[mi], &bh[p][2]);
                }
        }
        __syncthreads();
        if (c + 2 < NCHUNK) fill(c + 2, s);
    }

    const int row0 = m0 + wm * 64 + (lane >> 2);
    const int colb = n0 + wn * 32 + 2 * (lane & 3);
    #pragma unroll
    for (int ni = 0; ni < 4; ni++) {
        const int c = colb + ni * 8;
        const float b0 = bias[c], b1 = bias[c + 1];
        #pragma unroll
        for (int mi = 0; mi < 4; mi++) {
            #pragma unroll
            for (int half = 0; half < 2; half++) {
                const int r = row0 + mi * 16 + 8 * half;
                const float v0 = d[mi][ni][2 * half]     + b0;
                const float v1 = d[mi][ni][2 * half + 1] + b1;
                if (Cf) {
                    float2 w = {v0, v1};
                    *(float2*)(Cf + (size_t)r * GN + c) = w;
                } else {
                    uint32_t hv, lv;
                    split2(v0 * scale, v1 * scale, hv, lv);
                    ((uint32_t*)Ch)[(size_t)r * (GN / 2) + c / 2] = hv;
                    ((uint32_t*)Cl)[(size_t)r * (GN / 2) + c / 2] = lv;
                }
            }
        }
    }
}

// ---------------------------------------------------------------------------
// Flash attention (causal), split-bf16 MMAs, ldmatrix.x4 everywhere.
// ---------------------------------------------------------------------------
#define AST     36                  // u32 per row (144 B)
#define APL     (64 * AST)          // KV plane u32 (2304)
#define ASTAGE  (4 * APL)           // 9216 u32 = 36864 B
#define AQPL    (128 * AST)         // Q/P plane u32 (4608)
#define OFF_ST1U 0
#define OFF_ST0U ASTAGE
#define OFF_PU   (2 * ASTAGE)
#define ATT_SMEM_BYTES ((2 * ASTAGE + 2 * AQPL) * 4)   // 110592

__global__ __launch_bounds__(256, 2)
void attn_bf16s(const uint16_t* __restrict__ Qh, const uint16_t* __restrict__ Ql,
                const uint16_t* __restrict__ Kh, const uint16_t* __restrict__ Kl,
                const uint16_t* __restrict__ Vh, const uint16_t* __restrict__ Vl,
                uint16_t* __restrict__ Ch, uint16_t* __restrict__ Cl)
{
    extern __shared__ uint32_t smu[];
    const int tid  = threadIdx.x;
    const int lane = tid & 31;
    const int warp = tid >> 5;
    const int r    = lane >> 2;
    const int cth  = lane & 3;
    const int qi   = gridDim.x - 1 - blockIdx.x;   // heavy tiles first
    const int hd   = blockIdx.y;
    const int b    = blockIdx.z;
    const int q0   = qi * 128;

    const uint32_t smub = smem_u32(smu);
    const size_t hoff = (size_t)hd * 64;

    // ldmatrix lane offsets (bytes), stride 144
    const uint32_t koff = (uint32_t)(((lane & 7) + ((lane >> 4) << 3)) * 144 +
                                     (((lane >> 3) & 1) << 4));
    const uint32_t voff = (uint32_t)((lane & 15) * 144 + ((lane >> 4) << 4));
    const uint32_t poff = (uint32_t)((warp * 16 + (lane & 7) + ((lane >> 3) & 1) * 8)
                                     * 144 + ((lane >> 4) << 4));

    // Prologue: Q planes into ST1 area (group 0)
    #pragma unroll
    for (int i = 0; i < 4; i++) {
        const int id  = tid + i * 256;       // 0..1023
        const int row = id >> 3, seg = id & 7;
        const uint32_t so = (uint32_t)(row * 144 + seg * 16);
        CP16(smub + so, Qh + ((size_t)(b * Ll + q0 + row)) * Dm + hoff + seg * 8);
        CP16(smub + AQPL * 4 + so,
             Ql + ((size_t)(b * Ll + q0 + row)) * Dm + hoff + seg * 8);
    }
    asm volatile("cp.async.commit_group;");

    auto fillKV = [&](int kt, uint32_t dstB) {
        const int k0 = kt * 64;
        #pragma unroll
        for (int i = 0; i < 2; i++) {
            const int id  = tid + i * 256;   // 0..511
            const int row = id >> 3, seg = id & 7;
            const uint32_t so = (uint32_t)(row * 144 + seg * 16);
            const size_t g = ((size_t)(b * Ll + k0 + row)) * Dm + hoff + seg * 8;
            CP16(dstB + 0 * APL * 4 + so, Kh + g);
            CP16(dstB + 1 * APL * 4 + so, Kl + g);
            CP16(dstB + 2 * APL * 4 + so, Vh + g);
            CP16(dstB + 3 * APL * 4 + so, Vl + g);
        }
        asm volatile("cp.async.commit_group;");
    };

    fillKV(0, smub + OFF_ST0U * 4);

    asm volatile("cp.async.wait_group 1;" ::: "memory");
    __syncthreads();

    // Preload Q fragments (hi + lo), scalar (one-time)
    uint32_t qh[4][4], ql[4][4];
    {
        const uint32_t* qb = smu + (warp * 16 + r) * AST + cth;
        const uint32_t* qc = qb + AQPL;
        #pragma unroll
        for (int j = 0; j < 4; j++) {
            qh[j][0] = qb[j * 8];
            qh[j][1] = qb[8 * AST + j * 8];
            qh[j][2] = qb[j * 8 + 4];
            qh[j][3] = qb[8 * AST + j * 8 + 4];
            ql[j][0] = qc[j * 8];
            ql[j][1] = qc[8 * AST + j * 8];
            ql[j][2] = qc[j * 8 + 4];
            ql[j][3] = qc[8 * AST + j * 8 + 4];
        }
    }
    __syncthreads();

    const int ktmax = 2 * qi + 2;
    if (ktmax > 1) fillKV(1, smub + OFF_ST1U * 4);

    float m_i[2] = {-1e30f, -1e30f};
    float l_i[2] = {0.f, 0.f};
    float o[8][4];
    #pragma unroll
    for (int ni = 0; ni < 8; ni++)
        #pragma unroll
        for (int x = 0; x < 4; x++) o[ni][x] = 0.f;

    for (int kt = 0; kt < ktmax; kt++) {
        const int s = kt & 1;
        const uint32_t stB = smub + (s ? OFF_ST1U : OFF_ST0U) * 4;

        asm volatile("cp.async.wait_group 1;" ::: "memory");
        __syncthreads();

        // S = (Q/8) K^T  (3-product split-bf16)
        float sacc[8][4];
        #pragma unroll
        for (int ni = 0; ni < 8; ni++)
            #pragma unroll
            for (int x = 0; x < 4; x++) sacc[ni][x] = 0.f;

        #pragma unroll
        for (int j = 0; j < 4; j++) {
            #pragma unroll
            for (int nip = 0; nip < 4; nip++) {
                const uint32_t ka = stB + nip * 2304 + koff + j * 32;
                uint32_t bh[4], bl[4];
                ldsm_x4(bh, ka);
                mma_bf16(sacc[2 * nip],     qh[j], &bh[0]);
                mma_bf16(sacc[2 * nip + 1], qh[j], &bh[2]);
                mma_bf16(sacc[2 * nip],     ql[j], &bh[0]);
                mma_bf16(sacc[2 * nip + 1], ql[j], &bh[2]);
                ldsm_x4(bl, ka + APL * 4);
                mma_bf16(sacc[2 * nip],     qh[j], &bl[0]);
                mma_bf16(sacc[2 * nip + 1], qh[j], &bl[2]);
            }
        }

        const int k0 = kt * 64;
        if (k0 + 63 > q0) {      // causal mask near diagonal
            const int rowb = q0 + warp * 16 + r;
            #pragma unroll
            for (int ni = 0; ni < 8; ni++) {
                const int colb = k0 + ni * 8 + 2 * cth;
                #pragma unroll
                for (int x = 0; x < 4; x++) {
                    const int row = rowb + 8 * (x >> 1);
                    const int col = colb + (x & 1);
                    if (col > row) sacc[ni][x] = -1e30f;
                }
            }
        }

        // online softmax; P split to bf16 hi/lo planes in smem
        #pragma unroll
        for (int h = 0; h < 2; h++) {
            float mx = -1e30f;
            #pragma unroll
            for (int ni = 0; ni < 8; ni++)
                mx = fmaxf(mx, fmaxf(sacc[ni][2 * h], sacc[ni][2 * h + 1]));
            mx = fmaxf(mx, __shfl_xor_sync(0xffffffffu, mx, 1));
            mx = fmaxf(mx, __shfl_xor_sync(0xffffffffu, mx, 2));
            const float mnew  = fmaxf(m_i[h], mx);
            const float alpha = __expf(m_i[h] - mnew);
            float sum = 0.f;
            const int prow = warp * 16 + r + 8 * h;
            #pragma unroll
            for (int ni = 0; ni < 8; ni++) {
                const float p0 = __expf(sacc[ni][2 * h] - mnew);
                const float p1 = __expf(sacc[ni][2 * h + 1] - mnew);
                sum += p0 + p1;
                uint32_t hv, lv;
                split2(p0, p1, hv, lv);
                smu[OFF_PU + prow * AST + ni * 4 + cth] = hv;
                smu[OFF_PU + AQPL + prow * AST + ni * 4 + cth] = lv;
                o[ni][2 * h]     *= alpha;
                o[ni][2 * h + 1] *= alpha;
            }
            sum += __shfl_xor_sync(0xffffffffu, sum, 1);
            sum += __shfl_xor_sync(0xffffffffu, sum, 2);
            l_i[h] = l_i[h] * alpha + sum;
            m_i[h] = mnew;
        }
        __syncwarp();

        // O += P V  (P re-read via ldmatrix as A-frags; V via ldmatrix.trans)
        const uint32_t vB = stB + 2 * APL * 4;
        const uint32_t pB = smub + OFF_PU * 4 + poff;
        #pragma unroll
        for (int kk = 0; kk < 4; kk++) {
            uint32_t ph[4], pl[4];
            ldsm_x4(ph, pB + kk * 32);
            ldsm_x4(pl, pB + AQPL * 4 + kk * 32);
            #pragma unroll
            for (int nip = 0; nip < 4; nip++) {
                const uint32_t va = vB + kk * 2304 + nip * 32 + voff;
                uint32_t vh[4], vl[4];
                ldsm_x4_t(vh, va);
                mma_bf16(o[2 * nip],     ph, &vh[0]);
                mma_bf16(o[2 * nip + 1], ph, &vh[2]);
                mma_bf16(o[2 * nip],     pl, &vh[0]);
                mma_bf16(o[2 * nip + 1], pl, &vh[2]);
                ldsm_x4_t(vl, va + APL * 4);
                mma_bf16(o[2 * nip],     ph, &vl[0]);
                mma_bf16(o[2 * nip + 1], ph, &vl[2]);
            }
        }

        __syncthreads();
        if (kt + 2 < ktmax) fillKV(kt + 2, smub + (s ? OFF_ST1U : OFF_ST0U) * 4);
        else asm volatile("cp.async.commit_group;");
    }

    // normalize + split + write context planes
    #pragma unroll
    for (int h = 0; h < 2; h++) {
        const float inv = 1.0f / l_i[h];
        const int row = q0 + warp * 16 + r + 8 * h;
        const size_t base = ((size_t)(b * Ll + row)) * (Dm / 2) + hd * 32;
        #pragma unroll
        for (int ni = 0; ni < 8; ni++) {
            uint32_t hv, lv;
            split2(o[ni][2 * h] * inv, o[ni][2 * h + 1] * inv, hv, lv);
            ((uint32_t*)Ch)[base + ni * 4 + cth] = hv;
            ((uint32_t*)Cl)[base + ni * 4 + cth] = lv;
        }
    }
}

// ---------------------------------------------------------------------------
extern "C" void kernel_launch(void* const* d_in, const int* in_sizes, int n_in,
                              void* d_out, int out_size)
{
    const float* q    = (const float*)d_in[0];
    const float* k    = (const float*)d_in[1];
    const float* v    = (const float*)d_in[2];
    const float* wq_w = (const float*)d_in[3];
    const float* wq_b = (const float*)d_in[4];
    const float* wk_w = (const float*)d_in[5];
    const float* wk_b = (const float*)d_in[6];
    const float* wv_w = (const float*)d_in[7];
    const float* wv_b = (const float*)d_in[8];
    const float* wo_w = (const float*)d_in[9];
    const float* wo_b = (const float*)d_in[10];
    float* out = (float*)d_out;

    uint16_t* P;
    cudaGetSymbolAddress((void**)&P, g_buf);
    uint16_t* W = P + 14 * NPLANE;
    #define PLN(i) (P + (size_t)(i) * NPLANE)
    #define WPL(i) (W + (size_t)(i) * WPLANE)

    cudaFuncSetAttribute(gemm_bf16s, cudaFuncAttributeMaxDynamicSharedMemorySize,
                         GEMM_SMEM_BYTES);
    cudaFuncSetAttribute(attn_bf16s, cudaFuncAttributeMaxDynamicSharedMemorySize,
                         ATT_SMEM_BYTES);

    const int n8a = (int)(NPLANE / 8);   // 1048576
    const int n8w = (int)(WPLANE / 8);   // 131072

    Split4 sa;
    sa.in[0] = q; sa.hi[0] = PLN(0); sa.lo[0] = PLN(1);
    sa.in[1] = k; sa.hi[1] = PLN(2); sa.lo[1] = PLN(3);
    sa.in[2] = v; sa.hi[2] = PLN(4); sa.lo[2] = PLN(5);
    sa.in[3] = q; sa.hi[3] = PLN(0); sa.lo[3] = PLN(1);  // unused
    dim3 gs(n8a / 256, 3);
    split_multi<<<gs, 256>>>(sa, n8a);

    Split4 sw;
    sw.in[0] = wq_w; sw.hi[0] = WPL(0); sw.lo[0] = WPL(1);
    sw.in[1] = wk_w; sw.hi[1] = WPL(2); sw.lo[1] = WPL(3);
    sw.in[2] = wv_w; sw.hi[2] = WPL(4); sw.lo[2] = WPL(5);
    sw.in[3] = wo_w; sw.hi[3] = WPL(6); sw.lo[3] = WPL(7);
    dim3 gw(n8w / 256, 4);
    split_multi<<<gw, 256>>>(sw, n8w);

    dim3 gg(GN / 128, MTOT / 128);   // (8, 64)

    // projections -> bf16 hi/lo planes (Q pre-scaled by 1/8)
    gemm_bf16s<<<gg, 256, GEMM_SMEM_BYTES>>>(PLN(0), PLN(1), WPL(0), WPL(1),
                                             wq_b, nullptr, PLN(6), PLN(7), 0.125f);
    gemm_bf16s<<<gg, 256, GEMM_SMEM_BYTES>>>(PLN(2), PLN(3), WPL(2), WPL(3),
                                             wk_b, nullptr, PLN(8), PLN(9), 1.0f);
    gemm_bf16s<<<gg, 256, GEMM_SMEM_BYTES>>>(PLN(4), PLN(5), WPL(4), WPL(5),
                                             wv_b, nullptr, PLN(10), PLN(11), 1.0f);

    dim3 ga(Ll / 128, Hh, Bb);       // (16, 16, 4)
    attn_bf16s<<<ga, 256, ATT_SMEM_BYTES>>>(PLN(6), PLN(7), PLN(8), PLN(9),
                                            PLN(10), PLN(11), PLN(12), PLN(13));

    // output projection -> fp32 out
    gemm_bf16s<<<gg, 256, GEMM_SMEM_BYTES>>>(PLN(12), PLN(13), WPL(6), WPL(7),
                                             wo_b, out, nullptr, nullptr, 1.0f);
    #undef PLN
    #undef WPL
}